// round 1
// baseline (speedup 1.0000x reference)
#include <cuda_runtime.h>
#include <cstdint>

#define HH 128
#define NP 16384            // HH*HH pixels
#define GC 13               // grid cells per color axis (ceil(255/21))
#define NC (GC*GC*GC)       // 2197 cells
#define CELLW 21.0f         // cell width in color units
#define CAP 64              // max kept neighbors per pixel (E[nnz]~20, Poisson tail safe)
#define ETH 16.0f           // exponent threshold: K >= exp(-16) kept; tail mass ~2e-7
#define INV_TA (1.0f/160.0f)
#define INV_TB (1.0f/3.0f)
#define INV_TG (1.0f/3.0f)

// ---------------- device scratch (static, no allocation) ----------------
__device__ float  g_G[HH*HH];       // 1D Gaussian matrix (symmetric, shared H/W)
__device__ float  g_rs[HH];         // row sums of g_G (spatial norm = rs[r]*rs[c])
__device__ int    g_cellCnt[NC];
__device__ int    g_cellStart[NC+1];
__device__ int    g_cursor[NC];
__device__ int    g_sidx[NP];       // cell-sorted original pixel indices
__device__ float4 g_sfA[NP];        // sorted features (x/ta, y/ta, r/tb, g/tb)
__device__ float2 g_sfB[NP];        // (b/tb, bitcast(original index))
__device__ float2 g_ell[CAP*NP];    // slot-major: (.x = K value, .y = bitcast idx)
__device__ int    g_ellCnt[NP];
__device__ float  g_blNorm[NP];     // bilateral norm (row sum of kept K)
__device__ float  g_sm0[NP];        // softmax channel 0
__device__ float  g_T[NP];          // spatial row-pass intermediate
__device__ float  g_q[2*NP];        // state, interleaved NHWC (matches I/O layout)

// ---------------- setup kernels ----------------
__global__ void k_gauss() {
    int i = blockIdx.x, j = threadIdx.x;
    float d = (float)(i - j) * INV_TG;
    float g = __expf(-0.5f * d * d);
    g_G[i*HH + j] = g;
    __shared__ float s[HH];
    s[j] = g; __syncthreads();
    for (int o = 64; o > 0; o >>= 1) { if (j < o) s[j] += s[j+o]; __syncthreads(); }
    if (j == 0) g_rs[i] = s[0];
}

__global__ void k_init(const float* __restrict__ U) {
    int t = blockIdx.x * blockDim.x + threadIdx.x;
    if (t < 2*NP) g_q[t] = U[t];
    if (t < NC)   g_cellCnt[t] = 0;
}

__device__ __forceinline__ int cellOf(const float* __restrict__ rgb, int p) {
    float r = rgb[3*p], g = rgb[3*p+1], b = rgb[3*p+2];
    int c0 = (int)(r * (1.0f/CELLW)); c0 = c0 < 0 ? 0 : (c0 > GC-1 ? GC-1 : c0);
    int c1 = (int)(g * (1.0f/CELLW)); c1 = c1 < 0 ? 0 : (c1 > GC-1 ? GC-1 : c1);
    int c2 = (int)(b * (1.0f/CELLW)); c2 = c2 < 0 ? 0 : (c2 > GC-1 ? GC-1 : c2);
    return (c2*GC + c1)*GC + c0;
}

__global__ void k_count(const float* __restrict__ rgb) {
    int p = blockIdx.x * blockDim.x + threadIdx.x;
    if (p < NP) atomicAdd(&g_cellCnt[cellOf(rgb, p)], 1);
}

__global__ void k_scan() {   // 1 block, 256 threads, chunk=9 (256*9=2304 >= 2197)
    __shared__ int part[256];
    int t = threadIdx.x, base = t*9, s = 0, loc[9];
    for (int k = 0; k < 9; k++) {
        int c = base + k; int v = (c < NC) ? g_cellCnt[c] : 0;
        loc[k] = v; s += v;
    }
    part[t] = s; __syncthreads();
    if (t == 0) { int acc = 0; for (int i = 0; i < 256; i++) { int v = part[i]; part[i] = acc; acc += v; } }
    __syncthreads();
    int acc = part[t];
    for (int k = 0; k < 9; k++) {
        int c = base + k;
        if (c < NC) { g_cellStart[c] = acc; g_cursor[c] = acc; }
        acc += loc[k];
    }
    if (t == 255) g_cellStart[NC] = acc;
}

__global__ void k_scatter(const float* __restrict__ rgb) {
    int p = blockIdx.x * blockDim.x + threadIdx.x;
    if (p < NP) {
        int slot = atomicAdd(&g_cursor[cellOf(rgb, p)], 1);
        g_sidx[slot] = p;
    }
}

// sort each cell's members by original index (restores determinism after atomic
// scatter), then fill sorted feature arrays.
__global__ void k_cellsort(const float* __restrict__ rgb) {
    int c = blockIdx.x * blockDim.x + threadIdx.x;
    if (c >= NC) return;
    int st = g_cellStart[c], en = g_cellStart[c+1];
    for (int i = st + 1; i < en; i++) {
        int v = g_sidx[i]; int k = i - 1;
        while (k >= st && g_sidx[k] > v) { g_sidx[k+1] = g_sidx[k]; k--; }
        g_sidx[k+1] = v;
    }
    for (int s = st; s < en; s++) {
        int p = g_sidx[s];
        int y = p >> 7, x = p & 127;
        float fr = rgb[3*p] * INV_TB, fg = rgb[3*p+1] * INV_TB, fb = rgb[3*p+2] * INV_TB;
        g_sfA[s] = make_float4((float)x * INV_TA, (float)y * INV_TA, fr, fg);
        g_sfB[s] = make_float2(fb, __int_as_float(p));
    }
}

// warp per pixel: scan 27 neighboring color cells, keep K with exponent < ETH,
// compact into ELL rows via ballot. Deterministic (sorted cell order).
__global__ void k_build(const float* __restrict__ rgb) {
    int gtid = blockIdx.x * blockDim.x + threadIdx.x;
    int p = gtid >> 5;
    int lane = threadIdx.x & 31;
    if (p >= NP) return;

    int y = p >> 7, x = p & 127;
    float f0 = (float)x * INV_TA;
    float f1 = (float)y * INV_TA;
    float f2 = rgb[3*p]   * INV_TB;
    float f3 = rgb[3*p+1] * INV_TB;
    float f4 = rgb[3*p+2] * INV_TB;
    int c0 = (int)(rgb[3*p]   * (1.0f/CELLW)); c0 = c0 < 0 ? 0 : (c0 > GC-1 ? GC-1 : c0);
    int c1 = (int)(rgb[3*p+1] * (1.0f/CELLW)); c1 = c1 < 0 ? 0 : (c1 > GC-1 ? GC-1 : c1);
    int c2 = (int)(rgb[3*p+2] * (1.0f/CELLW)); c2 = c2 < 0 ? 0 : (c2 > GC-1 ? GC-1 : c2);

    int cnt = 0;
    float norm = 0.0f;
    for (int dz = -1; dz <= 1; dz++) {
        int cz = c2 + dz; if (cz < 0 || cz >= GC) continue;
        for (int dy = -1; dy <= 1; dy++) {
            int cy = c1 + dy; if (cy < 0 || cy >= GC) continue;
            for (int dx = -1; dx <= 1; dx++) {
                int cx = c0 + dx; if (cx < 0 || cx >= GC) continue;
                int cell = (cz*GC + cy)*GC + cx;
                int st = g_cellStart[cell], en = g_cellStart[cell+1];
                for (int s0 = st; s0 < en; s0 += 32) {
                    int s = s0 + lane;
                    bool keep = false; float val = 0.0f; int j = 0;
                    if (s < en) {
                        float4 fA = g_sfA[s];
                        float2 fB = g_sfB[s];
                        float d0 = f0 - fA.x, d1 = f1 - fA.y, d2 = f2 - fA.z,
                              d3 = f3 - fA.w, d4 = f4 - fB.x;
                        float e = 0.5f*(d0*d0 + d1*d1 + d2*d2 + d3*d3 + d4*d4);
                        if (e < ETH) { keep = true; val = __expf(-e); j = __float_as_int(fB.y); }
                    }
                    unsigned m = __ballot_sync(0xffffffffu, keep);
                    if (keep) {
                        int off = cnt + __popc(m & ((1u << lane) - 1u));
                        if (off < CAP) {
                            g_ell[off*NP + p] = make_float2(val, __int_as_float(j));
                            norm += val;
                        }
                    }
                    cnt += __popc(m);
                }
            }
        }
    }
    if (cnt > CAP) cnt = CAP;
    for (int o = 16; o > 0; o >>= 1) norm += __shfl_xor_sync(0xffffffffu, norm, o);
    if (lane == 0) { g_ellCnt[p] = cnt; g_blNorm[p] = norm; }
}

// ---------------- per-iteration kernels ----------------
// P: softmax (C=2 -> sigmoid) + spatial row pass  T = sm0 @ G
__global__ void k_P() {
    int r = blockIdx.x, t = threadIdx.x, p = r*HH + t;
    __shared__ float s[HH];
    float2 q = reinterpret_cast<const float2*>(g_q)[p];
    float sm = 1.0f / (1.0f + __expf(q.y - q.x));
    s[t] = sm;
    g_sm0[p] = sm;
    __syncthreads();
    float acc = 0.0f;
    #pragma unroll 8
    for (int k = 0; k < HH; k++) acc += s[k] * g_G[k*HH + t];
    g_T[p] = acc;
}

// Q: spatial column pass, bilateral SpMV, message passing, q update
__global__ void k_Q(const float* __restrict__ U,
                    const float* __restrict__ Ws,
                    const float* __restrict__ Wb,
                    const float* __restrict__ Cm,
                    float* __restrict__ outF, int last) {
    int r = blockIdx.x, t = threadIdx.x, p = r*HH + t;
    __shared__ float sg[HH];
    sg[t] = g_G[r*HH + t];
    __syncthreads();
    float sp = 0.0f;
    #pragma unroll 8
    for (int j = 0; j < HH; j++) sp += sg[j] * g_T[j*HH + t];
    sp /= (g_rs[r] * g_rs[t]);

    int cnt = g_ellCnt[p];
    float acc = 0.0f;
    #pragma unroll 4
    for (int k = 0; k < cnt; k++) {
        float2 e = g_ell[k*NP + p];
        acc += e.x * g_sm0[__float_as_int(e.y)];
    }
    float bl = acc / g_blNorm[p];

    float sp1 = 1.0f - sp, bl1 = 1.0f - bl;
    float mp0 = Ws[0]*sp + Ws[1]*sp1 + Wb[0]*bl + Wb[1]*bl1;
    float mp1 = Ws[2]*sp + Ws[3]*sp1 + Wb[2]*bl + Wb[3]*bl1;
    float pw0 = Cm[0]*mp0 + Cm[1]*mp1;
    float pw1 = Cm[2]*mp0 + Cm[3]*mp1;
    float q0 = U[2*p]   - pw0;
    float q1 = U[2*p+1] - pw1;
    g_q[2*p]   = q0;
    g_q[2*p+1] = q1;
    if (last) { outF[2*p] = q0; outF[2*p+1] = q1; }
}

// ---------------- launch ----------------
extern "C" void kernel_launch(void* const* d_in, const int* in_sizes, int n_in,
                              void* d_out, int out_size) {
    const float* U   = (const float*)d_in[0];
    const float* rgb = (const float*)d_in[1];
    const float* Ws  = (const float*)d_in[2];
    const float* Wb  = (const float*)d_in[3];
    const float* Cm  = (const float*)d_in[4];
    float* out = (float*)d_out;

    k_gauss   <<<HH, HH>>>();
    k_init    <<<(2*NP + 511)/512, 512>>>(U);
    k_count   <<<(NP + 511)/512, 512>>>(rgb);
    k_scan    <<<1, 256>>>();
    k_scatter <<<(NP + 511)/512, 512>>>(rgb);
    k_cellsort<<<(NC + 127)/128, 128>>>(rgb);
    k_build   <<<(NP*32 + 255)/256, 256>>>(rgb);

    for (int it = 0; it < 10; it++) {
        k_P<<<HH, HH>>>();
        k_Q<<<HH, HH>>>(U, Ws, Wb, Cm, out, it == 9);
    }
}